// round 10
// baseline (speedup 1.0000x reference)
#include <cuda_runtime.h>
#include <cuda_bf16.h>
#include <math.h>
#include <stdint.h>

#define DIM    512
#define NNEUR  4096
#define BT     8192   // B*T
#define NBLK1  (NNEUR / 128)   // 32 column-blocks in GEMM1

// ---------------- scratch (device globals; allocation-free) ----------------
__device__ float                       g_p2[NNEUR];
__device__ float                       g_x2[BT];
__device__ float                       g_cvec[DIM];
__device__ float                       g_S[BT];
__device__ __align__(16) float         g_psum[(size_t)BT * NBLK1];     // 1 MB
__device__ __align__(16) __nv_bfloat16 g_xb[BT * DIM];                 // 8 MB
__device__ __align__(16) __nv_bfloat16 g_pb[NNEUR * DIM];              // 4 MB
__device__ __align__(16) __nv_bfloat16 g_wvb[DIM * DIM];               // 0.5 MB
__device__ __align__(16) __nv_bfloat16 g_wob[DIM * DIM];               // 0.5 MB
__device__ __align__(16) __nv_bfloat16 g_valb[NNEUR * DIM];            // 4 MB  values
__device__ __align__(16) __nv_bfloat16 g_w2b[DIM * NNEUR];             // 4 MB  W2^T
__device__ __align__(16) __nv_bfloat16 g_attn[(size_t)BT * NNEUR];     // 64 MB (e = exp)

// ---------------- warp-mma helpers (base ISA: sm_80+, no 'a' suffix) -------
__device__ __forceinline__ uint32_t smem_to_u32(const void* p) {
    uint32_t a;
    asm("{ .reg .u64 t; cvta.to.shared.u64 t, %1; cvt.u32.u64 %0, t; }" : "=r"(a) : "l"(p));
    return a;
}
__device__ __forceinline__ void ldsm4(uint32_t& r0, uint32_t& r1, uint32_t& r2,
                                      uint32_t& r3, uint32_t addr) {
    asm volatile("ldmatrix.sync.aligned.m8n8.x4.shared.b16 {%0,%1,%2,%3}, [%4];"
                 : "=r"(r0), "=r"(r1), "=r"(r2), "=r"(r3) : "r"(addr));
}
__device__ __forceinline__ void mma16816(float* c, const uint32_t* a,
                                         uint32_t b0, uint32_t b1) {
    asm volatile(
        "mma.sync.aligned.m16n8k16.row.col.f32.bf16.bf16.f32 "
        "{%0,%1,%2,%3}, {%4,%5,%6,%7}, {%8,%9}, {%0,%1,%2,%3};"
        : "+f"(c[0]), "+f"(c[1]), "+f"(c[2]), "+f"(c[3])
        : "r"(a[0]), "r"(a[1]), "r"(a[2]), "r"(a[3]), "r"(b0), "r"(b1));
}
__device__ __forceinline__ void cp16(uint32_t dst, const void* src) {
    asm volatile("cp.async.cg.shared.global [%0], [%1], 16;" :: "r"(dst), "l"(src));
}
#define CP_COMMIT() asm volatile("cp.async.commit_group;" ::: "memory")
#define CP_WAIT(n)  asm volatile("cp.async.wait_group %0;" :: "n"(n) : "memory")

// SW128 swizzle for 128-byte rows (8 x 16B chunks): conflict-free ldmatrix
__device__ __forceinline__ uint32_t swz128(int row, int chunk) {
    return (uint32_t)(row * 128 + ((chunk ^ (row & 7)) << 4));
}

// ---------------------------------------------------------------------------
// bf16 mma_gemm: C[M,N] = A[M,K] @ B[N,K]^T, fp32 acc.
// BM=128, BN=128, BK=64, 256 threads = 8 warps (2 m x 4 n), warp tile 64x32.
// 3-stage cp.async pipeline (stage = 32 KB: A 16KB + B 16KB).  niter >= 2.
// EPI 1: interaction+exp -> bf16, per-block row sums -> psum.
// EPI 2: plain bf16 out.
// EPI 4: c / S[row] + bias[col] -> fp32 out.
// ---------------------------------------------------------------------------
static constexpr int MG_STAGES = 3;
static constexpr int MG_STAGE_B = 32768;
static constexpr int MG_SMEM   = MG_STAGES * MG_STAGE_B;   // 96 KB dynamic

template <int EPI>
__global__ __launch_bounds__(256, 2) void mma_gemm(
    const __nv_bfloat16* __restrict__ A, const __nv_bfloat16* __restrict__ B,
    void* __restrict__ Cv, int ldA, int ldB, int ldC, int niter,
    const float* __restrict__ rowv,   // EPI1: x2   | EPI4: S
    const float* __restrict__ p2,     // EPI1: p2
    const float* __restrict__ colv,   // EPI1: scale | EPI4: cvec bias
    float* __restrict__ psum)         // EPI1: per-block row sums
{
    extern __shared__ __align__(128) char dsm[];
    __shared__ float p2s[128], scs[128];
    __shared__ float bsum[4][128];

    const int tid  = threadIdx.x;
    const int lane = tid & 31, wid = tid >> 5;
    const int warp_m = wid >> 2, warp_n = wid & 3;
    const int bm = blockIdx.y * 128, bn = blockIdx.x * 128;

    if ((EPI == 1 || EPI == 4) && tid < 128) {
        if (EPI == 1) p2s[tid] = p2[bn + tid];
        scs[tid] = colv[bn + tid];
    }

    const int lrow  = tid >> 1;            // 0..127 (1 row / thread / matrix)
    const int lcb   = (tid & 1) * 4;       // chunk base 0 or 4
    const uint32_t su = smem_to_u32(dsm);

    auto issue = [&](int it) {
        const int slot = it % MG_STAGES;
        const int k0 = it * 64;            // bf16 elements
        const uint32_t ab = su + slot * MG_STAGE_B;
        const uint32_t bb = ab + 16384;
#pragma unroll
        for (int c = 0; c < 4; c++) {
            const int chunk = lcb + c;
            cp16(ab + swz128(lrow, chunk), A + (size_t)(bm + lrow) * ldA + k0 + chunk * 8);
            cp16(bb + swz128(lrow, chunk), B + (size_t)(bn + lrow) * ldB + k0 + chunk * 8);
        }
        CP_COMMIT();
    };

    issue(0);
    issue(1);

    float acc[4][4][4] = {};
    const int rin = lane & 7, matid = lane >> 3;

    for (int it = 0; it < niter; it++) {
        if (it == niter - 1) CP_WAIT(0); else CP_WAIT(1);
        __syncthreads();
        if (it + MG_STAGES - 1 < niter) issue(it + MG_STAGES - 1);

        const uint32_t a_s = su + (it % MG_STAGES) * MG_STAGE_B;
        const uint32_t b_s = a_s + 16384;
#pragma unroll
        for (int s = 0; s < 4; s++) {      // four k16 steps per BK=64
            uint32_t af[4][4], bf[2][4];
#pragma unroll
            for (int mb = 0; mb < 4; mb++) {
                const int row = warp_m * 64 + mb * 16 + (matid & 1) * 8 + rin;
                const int chk = s * 2 + (matid >> 1);
                ldsm4(af[mb][0], af[mb][1], af[mb][2], af[mb][3], a_s + swz128(row, chk));
            }
#pragma unroll
            for (int nb2 = 0; nb2 < 2; nb2++) {
                const int row = warp_n * 32 + nb2 * 16 + (matid >> 1) * 8 + rin;
                const int chk = s * 2 + (matid & 1);
                ldsm4(bf[nb2][0], bf[nb2][1], bf[nb2][2], bf[nb2][3], b_s + swz128(row, chk));
            }
#pragma unroll
            for (int mb = 0; mb < 4; mb++)
#pragma unroll
                for (int nb = 0; nb < 4; nb++)
                    mma16816(acc[mb][nb], af[mb],
                             bf[nb >> 1][(nb & 1) * 2], bf[nb >> 1][(nb & 1) * 2 + 1]);
        }
        __syncthreads();
    }

    // ---- epilogue ----
    const int g = lane >> 2, tig = lane & 3;
    float rs[4][2];
#pragma unroll
    for (int mb = 0; mb < 4; mb++) {
        const int r0 = warp_m * 64 + mb * 16 + g;      // local rows r0, r0+8
        float xa = 0.f, xb = 0.f, inva = 0.f, invb = 0.f;
        if (EPI == 1) { xa = rowv[bm + r0]; xb = rowv[bm + r0 + 8]; }
        if (EPI == 4) { inva = 1.0f / rowv[bm + r0]; invb = 1.0f / rowv[bm + r0 + 8]; }
        if (EPI == 1) { rs[mb][0] = 0.f; rs[mb][1] = 0.f; }
#pragma unroll
        for (int nb = 0; nb < 4; nb++) {
            const int cl = warp_n * 32 + nb * 8 + 2 * tig;
            const float* c = acc[mb][nb];
            if (EPI == 1) {
                const float p0 = p2s[cl], p1 = p2s[cl + 1];
                const float s0 = scs[cl], s1 = scs[cl + 1];
                const float q0 = fmaxf(xa - 2.f * c[0] + p0, 0.f);
                const float q1 = fmaxf(xa - 2.f * c[1] + p1, 0.f);
                const float q2 = fmaxf(xb - 2.f * c[2] + p0, 0.f);
                const float q3 = fmaxf(xb - 2.f * c[3] + p1, 0.f);
                const float e0 = __expf(s0 / (sqrtf(q0) + 0.1f));
                const float e1 = __expf(s1 / (sqrtf(q1) + 0.1f));
                const float e2 = __expf(s0 / (sqrtf(q2) + 0.1f));
                const float e3 = __expf(s1 / (sqrtf(q3) + 0.1f));
                rs[mb][0] += e0 + e1;
                rs[mb][1] += e2 + e3;
                __nv_bfloat16* Cb = reinterpret_cast<__nv_bfloat16*>(Cv);
                *reinterpret_cast<__nv_bfloat162*>(Cb + (size_t)(bm + r0) * ldC + bn + cl) =
                    __floats2bfloat162_rn(e0, e1);
                *reinterpret_cast<__nv_bfloat162*>(Cb + (size_t)(bm + r0 + 8) * ldC + bn + cl) =
                    __floats2bfloat162_rn(e2, e3);
            } else if (EPI == 2) {
                __nv_bfloat16* Cb = reinterpret_cast<__nv_bfloat16*>(Cv);
                *reinterpret_cast<__nv_bfloat162*>(Cb + (size_t)(bm + r0) * ldC + bn + cl) =
                    __floats2bfloat162_rn(c[0], c[1]);
                *reinterpret_cast<__nv_bfloat162*>(Cb + (size_t)(bm + r0 + 8) * ldC + bn + cl) =
                    __floats2bfloat162_rn(c[2], c[3]);
            } else {
                const float b0 = scs[cl], b1 = scs[cl + 1];
                float* Cf = reinterpret_cast<float*>(Cv);
                *reinterpret_cast<float2*>(Cf + (size_t)(bm + r0) * ldC + bn + cl) =
                    make_float2(fmaf(c[0], inva, b0), fmaf(c[1], inva, b1));
                *reinterpret_cast<float2*>(Cf + (size_t)(bm + r0 + 8) * ldC + bn + cl) =
                    make_float2(fmaf(c[2], invb, b0), fmaf(c[3], invb, b1));
            }
        }
    }

    if (EPI == 1) {
        // deterministic per-block row sums: reduce over tig (4 lanes), then warps
#pragma unroll
        for (int mb = 0; mb < 4; mb++) {
#pragma unroll
            for (int h = 0; h < 2; h++) {
                float v = rs[mb][h];
                v += __shfl_down_sync(0xffffffffu, v, 1);
                v += __shfl_down_sync(0xffffffffu, v, 2);
                if (tig == 0)
                    bsum[warp_n][warp_m * 64 + mb * 16 + h * 8 + g] = v;
            }
        }
        __syncthreads();
        if (tid < 128) {
            const float s = bsum[0][tid] + bsum[1][tid] + bsum[2][tid] + bsum[3][tid];
            psum[(size_t)(bm + tid) * NBLK1 + blockIdx.x] = s;
        }
    }
}

// S[row] = sum of 32 per-block partials (grid 32 x 256)
__global__ void rowsum2(const float* __restrict__ psum, float* __restrict__ S) {
    const int row = blockIdx.x * 256 + threadIdx.x;
    const float4* p = reinterpret_cast<const float4*>(psum + (size_t)row * NBLK1);
    float s = 0.f;
#pragma unroll
    for (int j = 0; j < NBLK1 / 4; j++) {
        const float4 v = p[j];
        s += v.x + v.y + v.z + v.w;
    }
    S[row] = s;
}

// ---------------------------------------------------------------------------
// conversions
// ---------------------------------------------------------------------------
// merged: x (rows < BT) and pos (rows >= BT): fp32 -> bf16 + row sum-of-squares
__global__ void conv_inputs(const float* __restrict__ x, const float* __restrict__ pos,
                            __nv_bfloat16* __restrict__ xb, __nv_bfloat16* __restrict__ pb,
                            float* __restrict__ x2, float* __restrict__ p2) {
    const int row = blockIdx.x;
    const int tid = threadIdx.x;
    const float* src;
    __nv_bfloat16* dst;
    float* o;
    if (row < BT) { src = x + (size_t)row * DIM; dst = xb + (size_t)row * DIM; o = x2 + row; }
    else {
        const int r = row - BT;
        src = pos + (size_t)r * DIM; dst = pb + (size_t)r * DIM; o = p2 + r;
    }
    const float4 v = reinterpret_cast<const float4*>(src)[tid];
    float s = v.x * v.x + v.y * v.y + v.z * v.z + v.w * v.w;
    union { uint2 u; __nv_bfloat162 h[2]; } w;
    w.h[0] = __floats2bfloat162_rn(v.x, v.y);
    w.h[1] = __floats2bfloat162_rn(v.z, v.w);
    reinterpret_cast<uint2*>(dst)[tid] = w.u;
#pragma unroll
    for (int off = 16; off > 0; off >>= 1) s += __shfl_down_sync(0xffffffffu, s, off);
    __shared__ float ws[4];
    if ((tid & 31) == 0) ws[tid >> 5] = s;
    __syncthreads();
    if (tid == 0) *o = ws[0] + ws[1] + ws[2] + ws[3];
}

// merged weight converts: rows < DIM -> w_v, rows >= DIM -> w_o
__global__ void conv_weights(const float* __restrict__ wv, const float* __restrict__ wo,
                             __nv_bfloat16* __restrict__ wvb, __nv_bfloat16* __restrict__ wob) {
    const int row = blockIdx.x;
    const int tid = threadIdx.x;
    const float* src = (row < DIM) ? wv + (size_t)row * DIM
                                   : wo + (size_t)(row - DIM) * DIM;
    __nv_bfloat16* dst = (row < DIM) ? wvb + (size_t)row * DIM
                                     : wob + (size_t)(row - DIM) * DIM;
    const float4 v = reinterpret_cast<const float4*>(src)[tid];
    union { uint2 u; __nv_bfloat162 h[2]; } w;
    w.h[0] = __floats2bfloat162_rn(v.x, v.y);
    w.h[1] = __floats2bfloat162_rn(v.z, v.w);
    reinterpret_cast<uint2*>(dst)[tid] = w.u;
}

// cvec[d] = b_o[d] + dot(w_o[d,:], b_v)
__global__ void cvec_kernel(const float* __restrict__ w_o, const float* __restrict__ b_v,
                            const float* __restrict__ b_o, float* __restrict__ cvec) {
    const int d = blockIdx.x;
    const int tid = threadIdx.x;
    float s = 0.f;
#pragma unroll
    for (int i = tid; i < DIM; i += 128) s += w_o[(size_t)d * DIM + i] * b_v[i];
#pragma unroll
    for (int off = 16; off > 0; off >>= 1) s += __shfl_down_sync(0xffffffffu, s, off);
    __shared__ float ws[4];
    if ((tid & 31) == 0) ws[tid >> 5] = s;
    __syncthreads();
    if (tid == 0) cvec[d] = b_o[d] + ws[0] + ws[1] + ws[2] + ws[3];
}

// ---------------------------------------------------------------------------
extern "C" void kernel_launch(void* const* d_in, const int* in_sizes, int n_in,
                              void* d_out, int out_size)
{
    const float* x     = (const float*)d_in[0];
    const float* pos   = (const float*)d_in[1];
    const float* scale = (const float*)d_in[2];
    const float* w_v   = (const float*)d_in[3];
    const float* b_v   = (const float*)d_in[4];
    const float* w_o   = (const float*)d_in[5];
    const float* b_o   = (const float*)d_in[6];
    float* out = (float*)d_out;

    static float* pp2 = nullptr;
    static float *px2, *pcv, *pS, *ppsum;
    static __nv_bfloat16 *pxb, *ppb, *pwvb, *pwob, *pvalb, *pw2b, *pattn;
    static cudaStream_t s1;
    static cudaEvent_t ev0, ev1;
    if (pp2 == nullptr) {
        cudaGetSymbolAddress((void**)&pp2,   g_p2);
        cudaGetSymbolAddress((void**)&px2,   g_x2);
        cudaGetSymbolAddress((void**)&pcv,   g_cvec);
        cudaGetSymbolAddress((void**)&pS,    g_S);
        cudaGetSymbolAddress((void**)&ppsum, g_psum);
        cudaGetSymbolAddress((void**)&pxb,   g_xb);
        cudaGetSymbolAddress((void**)&ppb,   g_pb);
        cudaGetSymbolAddress((void**)&pwvb,  g_wvb);
        cudaGetSymbolAddress((void**)&pwob,  g_wob);
        cudaGetSymbolAddress((void**)&pvalb, g_valb);
        cudaGetSymbolAddress((void**)&pw2b,  g_w2b);
        cudaGetSymbolAddress((void**)&pattn, g_attn);
        cudaFuncSetAttribute(mma_gemm<1>, cudaFuncAttributeMaxDynamicSharedMemorySize, MG_SMEM);
        cudaFuncSetAttribute(mma_gemm<2>, cudaFuncAttributeMaxDynamicSharedMemorySize, MG_SMEM);
        cudaFuncSetAttribute(mma_gemm<4>, cudaFuncAttributeMaxDynamicSharedMemorySize, MG_SMEM);
        cudaStreamCreateWithFlags(&s1, cudaStreamNonBlocking);
        cudaEventCreateWithFlags(&ev0, cudaEventDisableTiming);
        cudaEventCreateWithFlags(&ev1, cudaEventDisableTiming);
    }

    // input converts + norms (needed by both branches)
    conv_inputs<<<BT + NNEUR, 128>>>(x, pos, pxb, ppb, px2, pp2);
    cudaEventRecord(ev0, 0);

    // ---- side stream: weight chain (independent of GEMM1) ----
    cudaStreamWaitEvent(s1, ev0, 0);
    conv_weights<<<2 * DIM, 128, 0, s1>>>(w_v, w_o, pwvb, pwob);
    cvec_kernel <<<DIM,     128, 0, s1>>>(w_o, b_v, b_o, pcv);
    // values = pos @ w_v^T           (4096 x 512, K=512, bf16 out)
    mma_gemm<2><<<dim3(DIM / 128, NNEUR / 128), 256, MG_SMEM, s1>>>(
        ppb, pwvb, pvalb, DIM, DIM, DIM, DIM / 64, nullptr, nullptr, nullptr, nullptr);
    // W2^T = w_o @ values^T          (512 x 4096, K=512, bf16 out)
    mma_gemm<2><<<dim3(NNEUR / 128, DIM / 128), 256, MG_SMEM, s1>>>(
        pwob, pvalb, pw2b, DIM, DIM, NNEUR, DIM / 64, nullptr, nullptr, nullptr, nullptr);
    cudaEventRecord(ev1, s1);

    // ---- main stream: e = exp(f(x @ pos^T)) overlaps the side chain ----
    mma_gemm<1><<<dim3(NNEUR / 128, BT / 128), 256, MG_SMEM>>>(
        pxb, ppb, pattn, DIM, DIM, NNEUR, DIM / 64, px2, pp2, scale, ppsum);

    // S = row sums of e
    rowsum2<<<BT / 256, 256>>>(ppsum, pS);

    // join, then out = (e @ W2) / S + cvec   (8192 x 512, K=4096, fp32 out)
    cudaStreamWaitEvent(0, ev1, 0);
    mma_gemm<4><<<dim3(DIM / 128, BT / 128), 256, MG_SMEM>>>(
        pattn, pw2b, out, NNEUR, NNEUR, DIM, NNEUR / 64, pS, nullptr, pcv, nullptr);
}

// round 11
// speedup vs baseline: 1.3048x; 1.3048x over previous
#include <cuda_runtime.h>
#include <cuda_bf16.h>
#include <math.h>
#include <stdint.h>

#define DIM    512
#define NNEUR  4096
#define BT     8192   // B*T
#define NBLK1  (NNEUR / 128)   // 32 column-blocks in GEMM1

// ---------------- scratch (device globals; allocation-free) ----------------
__device__ float                       g_p2[NNEUR];
__device__ float                       g_x2[BT];
__device__ float                       g_cvec[DIM];
__device__ __align__(16) float         g_psum[(size_t)BT * NBLK1];     // 1 MB
__device__ __align__(16) __nv_bfloat16 g_xb[BT * DIM];                 // 8 MB
__device__ __align__(16) __nv_bfloat16 g_pb[NNEUR * DIM];              // 4 MB
__device__ __align__(16) __nv_bfloat16 g_wvb[DIM * DIM];               // 0.5 MB
__device__ __align__(16) __nv_bfloat16 g_wob[DIM * DIM];               // 0.5 MB
__device__ __align__(16) __nv_bfloat16 g_valb[NNEUR * DIM];            // 4 MB  values
__device__ __align__(16) __nv_bfloat16 g_w2b[DIM * NNEUR];             // 4 MB  W2^T
__device__ __align__(16) __nv_bfloat16 g_attn[(size_t)BT * NNEUR];     // 64 MB (e = exp)

// ---------------- warp-mma helpers (base ISA: sm_80+, no 'a' suffix) -------
__device__ __forceinline__ uint32_t smem_to_u32(const void* p) {
    uint32_t a;
    asm("{ .reg .u64 t; cvta.to.shared.u64 t, %1; cvt.u32.u64 %0, t; }" : "=r"(a) : "l"(p));
    return a;
}
__device__ __forceinline__ void ldsm4(uint32_t& r0, uint32_t& r1, uint32_t& r2,
                                      uint32_t& r3, uint32_t addr) {
    asm volatile("ldmatrix.sync.aligned.m8n8.x4.shared.b16 {%0,%1,%2,%3}, [%4];"
                 : "=r"(r0), "=r"(r1), "=r"(r2), "=r"(r3) : "r"(addr));
}
__device__ __forceinline__ void mma16816(float* c, const uint32_t* a,
                                         uint32_t b0, uint32_t b1) {
    asm volatile(
        "mma.sync.aligned.m16n8k16.row.col.f32.bf16.bf16.f32 "
        "{%0,%1,%2,%3}, {%4,%5,%6,%7}, {%8,%9}, {%0,%1,%2,%3};"
        : "+f"(c[0]), "+f"(c[1]), "+f"(c[2]), "+f"(c[3])
        : "r"(a[0]), "r"(a[1]), "r"(a[2]), "r"(a[3]), "r"(b0), "r"(b1));
}
__device__ __forceinline__ void cp16(uint32_t dst, const void* src) {
    asm volatile("cp.async.cg.shared.global [%0], [%1], 16;" :: "r"(dst), "l"(src));
}
#define CP_COMMIT() asm volatile("cp.async.commit_group;" ::: "memory")
#define CP_WAIT(n)  asm volatile("cp.async.wait_group %0;" :: "n"(n) : "memory")

// swizzled smem offset for 64B rows (4 x 16B chunks), conflict-free ldmatrix
__device__ __forceinline__ uint32_t swz_off(int row, int chunk) {
    return (uint32_t)(row * 64 + ((chunk ^ ((row >> 1) & 3)) << 4));
}

// ---------------------------------------------------------------------------
// bf16 mma_gemm: C[M,N] = A[M,K] @ B[N,K]^T, fp32 acc.
// BM=128, BN=128, BK=32, 256 threads = 8 warps (2 m x 4 n), warp tile 64x32.
// 3-stage cp.async pipeline.  Requires niter >= 2.
// EPI 1: interaction+exp -> bf16, per-block row sums -> psum.
// EPI 2: plain bf16 out.
// EPI 4: c * invS[row] + bias[col] -> fp32 out (invS computed from psum).
// ---------------------------------------------------------------------------
static constexpr int MG_STAGES = 3;
static constexpr int MG_SMEM   = MG_STAGES * 16384;   // 48 KB dynamic

template <int EPI>
__global__ __launch_bounds__(256) void mma_gemm(
    const __nv_bfloat16* __restrict__ A, const __nv_bfloat16* __restrict__ B,
    void* __restrict__ Cv, int ldA, int ldB, int ldC, int niter,
    const float* __restrict__ rowv,   // EPI1: x2
    const float* __restrict__ p2,     // EPI1: p2
    const float* __restrict__ colv,   // EPI1: scale | EPI4: cvec bias
    float* __restrict__ psum)         // EPI1: partial sums out | EPI4: partial sums in
{
    extern __shared__ __align__(128) char dsm[];
    __shared__ float p2s[128], scs[128];
    __shared__ float bsum[4][128];

    const int tid  = threadIdx.x;
    const int lane = tid & 31, wid = tid >> 5;
    const int warp_m = wid >> 2, warp_n = wid & 3;
    const int bm = blockIdx.y * 128, bn = blockIdx.x * 128;

    if ((EPI == 1 || EPI == 4) && tid < 128) {
        if (EPI == 1) p2s[tid] = p2[bn + tid];
        scs[tid] = colv[bn + tid];
    }
    if (EPI == 4 && tid < 128) {
        // invS for this CTA's 128 rows, from GEMM1's per-block partials
        // (same summation order as the old rowsum2 kernel -> bit-identical S)
        const float4* pp = reinterpret_cast<const float4*>(psum + (size_t)(bm + tid) * NBLK1);
        float s = 0.f;
#pragma unroll
        for (int j = 0; j < NBLK1 / 4; j++) {
            const float4 v = pp[j];
            s += v.x + v.y + v.z + v.w;
        }
        p2s[tid] = 1.0f / s;
    }

    const int lrow = tid >> 2;
    const int lchk = tid & 3;
    const uint32_t su = smem_to_u32(dsm);

    auto issue = [&](int it) {
        const int slot = it % MG_STAGES;
        const int k0 = it * 32;
        const uint32_t ab = su + slot * 16384;
        const uint32_t bb = ab + 8192;
#pragma unroll
        for (int h = 0; h < 2; h++) {
            const int r = lrow + h * 64;
            cp16(ab + swz_off(r, lchk), A + (size_t)(bm + r) * ldA + k0 + lchk * 8);
            cp16(bb + swz_off(r, lchk), B + (size_t)(bn + r) * ldB + k0 + lchk * 8);
        }
        CP_COMMIT();
    };

    issue(0);
    issue(1);

    float acc[4][4][4] = {};
    const int rin = lane & 7, matid = lane >> 3;

    for (int it = 0; it < niter; it++) {
        if (it == niter - 1) CP_WAIT(0); else CP_WAIT(1);
        __syncthreads();
        if (it + MG_STAGES - 1 < niter) issue(it + MG_STAGES - 1);

        const uint32_t a_s = su + (it % MG_STAGES) * 16384;
        const uint32_t b_s = a_s + 8192;
#pragma unroll
        for (int s = 0; s < 2; s++) {
            uint32_t af[4][4], bf[2][4];
#pragma unroll
            for (int mb = 0; mb < 4; mb++) {
                const int row = warp_m * 64 + mb * 16 + (matid & 1) * 8 + rin;
                const int chk = s * 2 + (matid >> 1);
                ldsm4(af[mb][0], af[mb][1], af[mb][2], af[mb][3], a_s + swz_off(row, chk));
            }
#pragma unroll
            for (int nb2 = 0; nb2 < 2; nb2++) {
                const int row = warp_n * 32 + nb2 * 16 + (matid >> 1) * 8 + rin;
                const int chk = s * 2 + (matid & 1);
                ldsm4(bf[nb2][0], bf[nb2][1], bf[nb2][2], bf[nb2][3], b_s + swz_off(row, chk));
            }
#pragma unroll
            for (int mb = 0; mb < 4; mb++)
#pragma unroll
                for (int nb = 0; nb < 4; nb++)
                    mma16816(acc[mb][nb], af[mb],
                             bf[nb >> 1][(nb & 1) * 2], bf[nb >> 1][(nb & 1) * 2 + 1]);
        }
    }

    // ---- epilogue ----
    const int g = lane >> 2, tig = lane & 3;
    float rs[4][2];
#pragma unroll
    for (int mb = 0; mb < 4; mb++) {
        const int r0 = warp_m * 64 + mb * 16 + g;      // local rows r0, r0+8
        float xa = 0.f, xb = 0.f, inva = 0.f, invb = 0.f;
        if (EPI == 1) { xa = rowv[bm + r0]; xb = rowv[bm + r0 + 8]; }
        if (EPI == 4) { inva = p2s[r0]; invb = p2s[r0 + 8]; }
        if (EPI == 1) { rs[mb][0] = 0.f; rs[mb][1] = 0.f; }
#pragma unroll
        for (int nb = 0; nb < 4; nb++) {
            const int cl = warp_n * 32 + nb * 8 + 2 * tig;
            const float* c = acc[mb][nb];
            if (EPI == 1) {
                const float p0 = p2s[cl], p1 = p2s[cl + 1];
                const float s0 = scs[cl], s1 = scs[cl + 1];
                const float q0 = fmaxf(xa - 2.f * c[0] + p0, 0.f);
                const float q1 = fmaxf(xa - 2.f * c[1] + p1, 0.f);
                const float q2 = fmaxf(xb - 2.f * c[2] + p0, 0.f);
                const float q3 = fmaxf(xb - 2.f * c[3] + p1, 0.f);
                const float e0 = __expf(s0 / (sqrtf(q0) + 0.1f));
                const float e1 = __expf(s1 / (sqrtf(q1) + 0.1f));
                const float e2 = __expf(s0 / (sqrtf(q2) + 0.1f));
                const float e3 = __expf(s1 / (sqrtf(q3) + 0.1f));
                rs[mb][0] += e0 + e1;
                rs[mb][1] += e2 + e3;
                __nv_bfloat16* Cb = reinterpret_cast<__nv_bfloat16*>(Cv);
                *reinterpret_cast<__nv_bfloat162*>(Cb + (size_t)(bm + r0) * ldC + bn + cl) =
                    __floats2bfloat162_rn(e0, e1);
                *reinterpret_cast<__nv_bfloat162*>(Cb + (size_t)(bm + r0 + 8) * ldC + bn + cl) =
                    __floats2bfloat162_rn(e2, e3);
            } else if (EPI == 2) {
                __nv_bfloat16* Cb = reinterpret_cast<__nv_bfloat16*>(Cv);
                *reinterpret_cast<__nv_bfloat162*>(Cb + (size_t)(bm + r0) * ldC + bn + cl) =
                    __floats2bfloat162_rn(c[0], c[1]);
                *reinterpret_cast<__nv_bfloat162*>(Cb + (size_t)(bm + r0 + 8) * ldC + bn + cl) =
                    __floats2bfloat162_rn(c[2], c[3]);
            } else {
                const float b0 = scs[cl], b1 = scs[cl + 1];
                float* Cf = reinterpret_cast<float*>(Cv);
                *reinterpret_cast<float2*>(Cf + (size_t)(bm + r0) * ldC + bn + cl) =
                    make_float2(fmaf(c[0], inva, b0), fmaf(c[1], inva, b1));
                *reinterpret_cast<float2*>(Cf + (size_t)(bm + r0 + 8) * ldC + bn + cl) =
                    make_float2(fmaf(c[2], invb, b0), fmaf(c[3], invb, b1));
            }
        }
    }

    if (EPI == 1) {
        // deterministic per-block row sums: reduce over tig (4 lanes), then warps
#pragma unroll
        for (int mb = 0; mb < 4; mb++) {
#pragma unroll
            for (int h = 0; h < 2; h++) {
                float v = rs[mb][h];
                v += __shfl_down_sync(0xffffffffu, v, 1);
                v += __shfl_down_sync(0xffffffffu, v, 2);
                if (tig == 0)
                    bsum[warp_n][warp_m * 64 + mb * 16 + h * 8 + g] = v;
            }
        }
        __syncthreads();
        if (tid < 128) {
            const float s = bsum[0][tid] + bsum[1][tid] + bsum[2][tid] + bsum[3][tid];
            psum[(size_t)(bm + tid) * NBLK1 + blockIdx.x] = s;
        }
    }
}

// ---------------------------------------------------------------------------
// conversions
// ---------------------------------------------------------------------------
// merged: x (rows < BT) and pos (rows >= BT): fp32 -> bf16 + row sum-of-squares
__global__ void conv_inputs(const float* __restrict__ x, const float* __restrict__ pos,
                            __nv_bfloat16* __restrict__ xb, __nv_bfloat16* __restrict__ pb,
                            float* __restrict__ x2, float* __restrict__ p2) {
    const int row = blockIdx.x;
    const int tid = threadIdx.x;
    const float* src;
    __nv_bfloat16* dst;
    float* o;
    if (row < BT) { src = x + (size_t)row * DIM; dst = xb + (size_t)row * DIM; o = x2 + row; }
    else {
        const int r = row - BT;
        src = pos + (size_t)r * DIM; dst = pb + (size_t)r * DIM; o = p2 + r;
    }
    const float4 v = reinterpret_cast<const float4*>(src)[tid];
    float s = v.x * v.x + v.y * v.y + v.z * v.z + v.w * v.w;
    union { uint2 u; __nv_bfloat162 h[2]; } w;
    w.h[0] = __floats2bfloat162_rn(v.x, v.y);
    w.h[1] = __floats2bfloat162_rn(v.z, v.w);
    reinterpret_cast<uint2*>(dst)[tid] = w.u;
#pragma unroll
    for (int off = 16; off > 0; off >>= 1) s += __shfl_down_sync(0xffffffffu, s, off);
    __shared__ float ws[4];
    if ((tid & 31) == 0) ws[tid >> 5] = s;
    __syncthreads();
    if (tid == 0) *o = ws[0] + ws[1] + ws[2] + ws[3];
}

// merged weight converts: rows < DIM -> w_v, rows >= DIM -> w_o
__global__ void conv_weights(const float* __restrict__ wv, const float* __restrict__ wo,
                             __nv_bfloat16* __restrict__ wvb, __nv_bfloat16* __restrict__ wob) {
    const int row = blockIdx.x;
    const int tid = threadIdx.x;
    const float* src = (row < DIM) ? wv + (size_t)row * DIM
                                   : wo + (size_t)(row - DIM) * DIM;
    __nv_bfloat16* dst = (row < DIM) ? wvb + (size_t)row * DIM
                                     : wob + (size_t)(row - DIM) * DIM;
    const float4 v = reinterpret_cast<const float4*>(src)[tid];
    union { uint2 u; __nv_bfloat162 h[2]; } w;
    w.h[0] = __floats2bfloat162_rn(v.x, v.y);
    w.h[1] = __floats2bfloat162_rn(v.z, v.w);
    reinterpret_cast<uint2*>(dst)[tid] = w.u;
}

// cvec[d] = b_o[d] + dot(w_o[d,:], b_v)
__global__ void cvec_kernel(const float* __restrict__ w_o, const float* __restrict__ b_v,
                            const float* __restrict__ b_o, float* __restrict__ cvec) {
    const int d = blockIdx.x;
    const int tid = threadIdx.x;
    float s = 0.f;
#pragma unroll
    for (int i = tid; i < DIM; i += 128) s += w_o[(size_t)d * DIM + i] * b_v[i];
#pragma unroll
    for (int off = 16; off > 0; off >>= 1) s += __shfl_down_sync(0xffffffffu, s, off);
    __shared__ float ws[4];
    if ((tid & 31) == 0) ws[tid >> 5] = s;
    __syncthreads();
    if (tid == 0) cvec[d] = b_o[d] + ws[0] + ws[1] + ws[2] + ws[3];
}

// ---------------------------------------------------------------------------
extern "C" void kernel_launch(void* const* d_in, const int* in_sizes, int n_in,
                              void* d_out, int out_size)
{
    const float* x     = (const float*)d_in[0];
    const float* pos   = (const float*)d_in[1];
    const float* scale = (const float*)d_in[2];
    const float* w_v   = (const float*)d_in[3];
    const float* b_v   = (const float*)d_in[4];
    const float* w_o   = (const float*)d_in[5];
    const float* b_o   = (const float*)d_in[6];
    float* out = (float*)d_out;

    static float* pp2 = nullptr;
    static float *px2, *pcv, *ppsum;
    static __nv_bfloat16 *pxb, *ppb, *pwvb, *pwob, *pvalb, *pw2b, *pattn;
    static cudaStream_t s1;
    static cudaEvent_t ev0, ev1;
    if (pp2 == nullptr) {
        cudaGetSymbolAddress((void**)&pp2,   g_p2);
        cudaGetSymbolAddress((void**)&px2,   g_x2);
        cudaGetSymbolAddress((void**)&pcv,   g_cvec);
        cudaGetSymbolAddress((void**)&ppsum, g_psum);
        cudaGetSymbolAddress((void**)&pxb,   g_xb);
        cudaGetSymbolAddress((void**)&ppb,   g_pb);
        cudaGetSymbolAddress((void**)&pwvb,  g_wvb);
        cudaGetSymbolAddress((void**)&pwob,  g_wob);
        cudaGetSymbolAddress((void**)&pvalb, g_valb);
        cudaGetSymbolAddress((void**)&pw2b,  g_w2b);
        cudaGetSymbolAddress((void**)&pattn, g_attn);
        cudaFuncSetAttribute(mma_gemm<1>, cudaFuncAttributeMaxDynamicSharedMemorySize, MG_SMEM);
        cudaFuncSetAttribute(mma_gemm<2>, cudaFuncAttributeMaxDynamicSharedMemorySize, MG_SMEM);
        cudaFuncSetAttribute(mma_gemm<4>, cudaFuncAttributeMaxDynamicSharedMemorySize, MG_SMEM);
        cudaStreamCreateWithFlags(&s1, cudaStreamNonBlocking);
        cudaEventCreateWithFlags(&ev0, cudaEventDisableTiming);
        cudaEventCreateWithFlags(&ev1, cudaEventDisableTiming);
    }

    // input converts + norms (needed by both branches)
    conv_inputs<<<BT + NNEUR, 128>>>(x, pos, pxb, ppb, px2, pp2);
    cudaEventRecord(ev0, 0);

    // ---- side stream: weight chain (independent of GEMM1) ----
    cudaStreamWaitEvent(s1, ev0, 0);
    conv_weights<<<2 * DIM, 128, 0, s1>>>(w_v, w_o, pwvb, pwob);
    cvec_kernel <<<DIM,     128, 0, s1>>>(w_o, b_v, b_o, pcv);
    // values = pos @ w_v^T           (4096 x 512, K=512, bf16 out)
    mma_gemm<2><<<dim3(DIM / 128, NNEUR / 128), 256, MG_SMEM, s1>>>(
        ppb, pwvb, pvalb, DIM, DIM, DIM, DIM / 32, nullptr, nullptr, nullptr, nullptr);
    // W2^T = w_o @ values^T          (512 x 4096, K=512, bf16 out)
    mma_gemm<2><<<dim3(NNEUR / 128, DIM / 128), 256, MG_SMEM, s1>>>(
        pwob, pvalb, pw2b, DIM, DIM, NNEUR, DIM / 32, nullptr, nullptr, nullptr, nullptr);
    cudaEventRecord(ev1, s1);

    // ---- main stream: e = exp(f(x @ pos^T)) overlaps the side chain ----
    mma_gemm<1><<<dim3(NNEUR / 128, BT / 128), 256, MG_SMEM>>>(
        pxb, ppb, pattn, DIM, DIM, NNEUR, DIM / 32, px2, pp2, scale, ppsum);

    // join, then out = (e @ W2) / S + cvec   (8192 x 512, K=4096, fp32 out;
    // S folded into the GEMM's prologue from psum)
    cudaStreamWaitEvent(0, ev1, 0);
    mma_gemm<4><<<dim3(DIM / 128, BT / 128), 256, MG_SMEM>>>(
        pattn, pw2b, out, NNEUR, NNEUR, DIM, NNEUR / 32, nullptr, nullptr, pcv, ppsum);
}

// round 12
// speedup vs baseline: 1.3486x; 1.0335x over previous
#include <cuda_runtime.h>
#include <cuda_bf16.h>
#include <math.h>
#include <stdint.h>

#define DIM    512
#define NNEUR  4096
#define BT     8192   // B*T
#define NBLK1  (NNEUR / 128)   // 32 column-blocks in GEMM1

// ---------------- scratch (device globals; allocation-free) ----------------
__device__ float                       g_p2[NNEUR];
__device__ float                       g_x2[BT];
__device__ float                       g_cvec[DIM];
__device__ __align__(16) float         g_psum[(size_t)BT * NBLK1];     // 1 MB
__device__ __align__(16) __nv_bfloat16 g_xb[BT * DIM];                 // 8 MB
__device__ __align__(16) __nv_bfloat16 g_pb[NNEUR * DIM];              // 4 MB
__device__ __align__(16) __nv_bfloat16 g_wvb[DIM * DIM];               // 0.5 MB
__device__ __align__(16) __nv_bfloat16 g_wob[DIM * DIM];               // 0.5 MB
__device__ __align__(16) __nv_bfloat16 g_valb[NNEUR * DIM];            // 4 MB  values
__device__ __align__(16) __nv_bfloat16 g_w2b[DIM * NNEUR];             // 4 MB  W2^T
__device__ __align__(16) __nv_bfloat16 g_attn[(size_t)BT * NNEUR];     // 64 MB (e = exp)

// ---------------- warp-mma helpers (base ISA: sm_80+, no 'a' suffix) -------
__device__ __forceinline__ uint32_t smem_to_u32(const void* p) {
    uint32_t a;
    asm("{ .reg .u64 t; cvta.to.shared.u64 t, %1; cvt.u32.u64 %0, t; }" : "=r"(a) : "l"(p));
    return a;
}
__device__ __forceinline__ void ldsm4(uint32_t& r0, uint32_t& r1, uint32_t& r2,
                                      uint32_t& r3, uint32_t addr) {
    asm volatile("ldmatrix.sync.aligned.m8n8.x4.shared.b16 {%0,%1,%2,%3}, [%4];"
                 : "=r"(r0), "=r"(r1), "=r"(r2), "=r"(r3) : "r"(addr));
}
__device__ __forceinline__ void mma16816(float* c, const uint32_t* a,
                                         uint32_t b0, uint32_t b1) {
    asm volatile(
        "mma.sync.aligned.m16n8k16.row.col.f32.bf16.bf16.f32 "
        "{%0,%1,%2,%3}, {%4,%5,%6,%7}, {%8,%9}, {%0,%1,%2,%3};"
        : "+f"(c[0]), "+f"(c[1]), "+f"(c[2]), "+f"(c[3])
        : "r"(a[0]), "r"(a[1]), "r"(a[2]), "r"(a[3]), "r"(b0), "r"(b1));
}
__device__ __forceinline__ void cp16(uint32_t dst, const void* src) {
    asm volatile("cp.async.cg.shared.global [%0], [%1], 16;" :: "r"(dst), "l"(src));
}
#define CP_COMMIT() asm volatile("cp.async.commit_group;" ::: "memory")
#define CP_WAIT(n)  asm volatile("cp.async.wait_group %0;" :: "n"(n) : "memory")

// swizzled smem offset for 64B rows (4 x 16B chunks), conflict-free ldmatrix
__device__ __forceinline__ uint32_t swz_off(int row, int chunk) {
    return (uint32_t)(row * 64 + ((chunk ^ ((row >> 1) & 3)) << 4));
}

// ---------------------------------------------------------------------------
// bf16 mma_gemm: C[M,N] = A[M,K] @ B[N,K]^T, fp32 acc.
// BM=128, BN=128, BK=32, 256 threads = 8 warps (2 m x 4 n), warp tile 64x32.
// 4-stage cp.async pipeline, mainloop unrolled x4 so stage slots/addresses are
// compile-time constants.  Requires niter >= 3 and niter % 4 == 0.
// EPI 1: interaction+exp -> bf16, per-block row sums -> psum.
// EPI 2: plain bf16 out.
// EPI 4: c * invS[row] + bias[col] -> fp32 out (invS computed from psum).
// ---------------------------------------------------------------------------
static constexpr int MG_STAGES = 4;
static constexpr int MG_SMEM   = MG_STAGES * 16384;   // 64 KB dynamic

template <int EPI>
__global__ __launch_bounds__(256) void mma_gemm(
    const __nv_bfloat16* __restrict__ A, const __nv_bfloat16* __restrict__ B,
    void* __restrict__ Cv, int ldA, int ldB, int ldC, int niter,
    const float* __restrict__ rowv,   // EPI1: x2
    const float* __restrict__ p2,     // EPI1: p2
    const float* __restrict__ colv,   // EPI1: scale | EPI4: cvec bias
    float* __restrict__ psum)         // EPI1: partial sums out | EPI4: partial sums in
{
    extern __shared__ __align__(128) char dsm[];
    __shared__ float p2s[128], scs[128];
    __shared__ float bsum[4][128];

    const int tid  = threadIdx.x;
    const int lane = tid & 31, wid = tid >> 5;
    const int warp_m = wid >> 2, warp_n = wid & 3;
    const int bm = blockIdx.y * 128, bn = blockIdx.x * 128;

    if ((EPI == 1 || EPI == 4) && tid < 128) {
        if (EPI == 1) p2s[tid] = p2[bn + tid];
        scs[tid] = colv[bn + tid];
    }

    const int lrow = tid >> 2;
    const int lchk = tid & 3;
    const uint32_t su = smem_to_u32(dsm);

    // issue stage for iteration it into compile-time slot (it & 3)
    auto issue = [&](int slot, int it) {
        const int k0 = it * 32;
        const uint32_t ab = su + slot * 16384;
        const uint32_t bb = ab + 8192;
#pragma unroll
        for (int h = 0; h < 2; h++) {
            const int r = lrow + h * 64;
            cp16(ab + swz_off(r, lchk), A + (size_t)(bm + r) * ldA + k0 + lchk * 8);
            cp16(bb + swz_off(r, lchk), B + (size_t)(bn + r) * ldB + k0 + lchk * 8);
        }
        CP_COMMIT();
    };

    issue(0, 0);
    issue(1, 1);
    issue(2, 2);

    if (EPI == 4 && tid < 128) {
        // invS for this CTA's 128 rows (overlaps the prefetches above);
        // same summation order as before -> bit-identical S
        const float4* pp = reinterpret_cast<const float4*>(psum + (size_t)(bm + tid) * NBLK1);
        float s = 0.f;
#pragma unroll
        for (int j = 0; j < NBLK1 / 4; j++) {
            const float4 v = pp[j];
            s += v.x + v.y + v.z + v.w;
        }
        p2s[tid] = 1.0f / s;
    }

    float acc[4][4][4] = {};
    const int rin = lane & 7, matid = lane >> 3;

    for (int itb = 0; itb < niter; itb += 4) {
#pragma unroll
        for (int j = 0; j < 4; j++) {          // j compile-time -> slot folded
            const int it = itb + j;
            CP_WAIT(2);                        // stage it landed (<=2 pending)
            __syncthreads();
            if (it + 3 < niter) issue((j + 3) & 3, it + 3);

            const uint32_t a_s = su + j * 16384;
            const uint32_t b_s = a_s + 8192;
#pragma unroll
            for (int s = 0; s < 2; s++) {
                uint32_t af[4][4], bf[2][4];
#pragma unroll
                for (int mb = 0; mb < 4; mb++) {
                    const int row = warp_m * 64 + mb * 16 + (matid & 1) * 8 + rin;
                    const int chk = s * 2 + (matid >> 1);
                    ldsm4(af[mb][0], af[mb][1], af[mb][2], af[mb][3], a_s + swz_off(row, chk));
                }
#pragma unroll
                for (int nb2 = 0; nb2 < 2; nb2++) {
                    const int row = warp_n * 32 + nb2 * 16 + (matid >> 1) * 8 + rin;
                    const int chk = s * 2 + (matid & 1);
                    ldsm4(bf[nb2][0], bf[nb2][1], bf[nb2][2], bf[nb2][3], b_s + swz_off(row, chk));
                }
#pragma unroll
                for (int mb = 0; mb < 4; mb++)
#pragma unroll
                    for (int nb = 0; nb < 4; nb++)
                        mma16816(acc[mb][nb], af[mb],
                                 bf[nb >> 1][(nb & 1) * 2], bf[nb >> 1][(nb & 1) * 2 + 1]);
            }
        }
    }

    // ---- epilogue ----
    const int g = lane >> 2, tig = lane & 3;
    float rs[4][2];
#pragma unroll
    for (int mb = 0; mb < 4; mb++) {
        const int r0 = warp_m * 64 + mb * 16 + g;      // local rows r0, r0+8
        float xa = 0.f, xb = 0.f, inva = 0.f, invb = 0.f;
        if (EPI == 1) { xa = rowv[bm + r0]; xb = rowv[bm + r0 + 8]; }
        if (EPI == 4) { inva = p2s[r0]; invb = p2s[r0 + 8]; }
        if (EPI == 1) { rs[mb][0] = 0.f; rs[mb][1] = 0.f; }
#pragma unroll
        for (int nb = 0; nb < 4; nb++) {
            const int cl = warp_n * 32 + nb * 8 + 2 * tig;
            const float* c = acc[mb][nb];
            if (EPI == 1) {
                const float p0 = p2s[cl], p1 = p2s[cl + 1];
                const float s0 = scs[cl], s1 = scs[cl + 1];
                const float q0 = fmaxf(xa - 2.f * c[0] + p0, 0.f);
                const float q1 = fmaxf(xa - 2.f * c[1] + p1, 0.f);
                const float q2 = fmaxf(xb - 2.f * c[2] + p0, 0.f);
                const float q3 = fmaxf(xb - 2.f * c[3] + p1, 0.f);
                const float e0 = __expf(s0 / (sqrtf(q0) + 0.1f));
                const float e1 = __expf(s1 / (sqrtf(q1) + 0.1f));
                const float e2 = __expf(s0 / (sqrtf(q2) + 0.1f));
                const float e3 = __expf(s1 / (sqrtf(q3) + 0.1f));
                rs[mb][0] += e0 + e1;
                rs[mb][1] += e2 + e3;
                __nv_bfloat16* Cb = reinterpret_cast<__nv_bfloat16*>(Cv);
                *reinterpret_cast<__nv_bfloat162*>(Cb + (size_t)(bm + r0) * ldC + bn + cl) =
                    __floats2bfloat162_rn(e0, e1);
                *reinterpret_cast<__nv_bfloat162*>(Cb + (size_t)(bm + r0 + 8) * ldC + bn + cl) =
                    __floats2bfloat162_rn(e2, e3);
            } else if (EPI == 2) {
                __nv_bfloat16* Cb = reinterpret_cast<__nv_bfloat16*>(Cv);
                *reinterpret_cast<__nv_bfloat162*>(Cb + (size_t)(bm + r0) * ldC + bn + cl) =
                    __floats2bfloat162_rn(c[0], c[1]);
                *reinterpret_cast<__nv_bfloat162*>(Cb + (size_t)(bm + r0 + 8) * ldC + bn + cl) =
                    __floats2bfloat162_rn(c[2], c[3]);
            } else {
                const float b0 = scs[cl], b1 = scs[cl + 1];
                float* Cf = reinterpret_cast<float*>(Cv);
                *reinterpret_cast<float2*>(Cf + (size_t)(bm + r0) * ldC + bn + cl) =
                    make_float2(fmaf(c[0], inva, b0), fmaf(c[1], inva, b1));
                *reinterpret_cast<float2*>(Cf + (size_t)(bm + r0 + 8) * ldC + bn + cl) =
                    make_float2(fmaf(c[2], invb, b0), fmaf(c[3], invb, b1));
            }
        }
    }

    if (EPI == 1) {
        // deterministic per-block row sums: reduce over tig (4 lanes), then warps
#pragma unroll
        for (int mb = 0; mb < 4; mb++) {
#pragma unroll
            for (int h = 0; h < 2; h++) {
                float v = rs[mb][h];
                v += __shfl_down_sync(0xffffffffu, v, 1);
                v += __shfl_down_sync(0xffffffffu, v, 2);
                if (tig == 0)
                    bsum[warp_n][warp_m * 64 + mb * 16 + h * 8 + g] = v;
            }
        }
        __syncthreads();
        if (tid < 128) {
            const float s = bsum[0][tid] + bsum[1][tid] + bsum[2][tid] + bsum[3][tid];
            psum[(size_t)(bm + tid) * NBLK1 + blockIdx.x] = s;
        }
    }
}

// ---------------------------------------------------------------------------
// conversions
// ---------------------------------------------------------------------------
// merged: x (rows < BT) and pos (rows >= BT): fp32 -> bf16 + row sum-of-squares
__global__ void conv_inputs(const float* __restrict__ x, const float* __restrict__ pos,
                            __nv_bfloat16* __restrict__ xb, __nv_bfloat16* __restrict__ pb,
                            float* __restrict__ x2, float* __restrict__ p2) {
    const int row = blockIdx.x;
    const int tid = threadIdx.x;
    const float* src;
    __nv_bfloat16* dst;
    float* o;
    if (row < BT) { src = x + (size_t)row * DIM; dst = xb + (size_t)row * DIM; o = x2 + row; }
    else {
        const int r = row - BT;
        src = pos + (size_t)r * DIM; dst = pb + (size_t)r * DIM; o = p2 + r;
    }
    const float4 v = reinterpret_cast<const float4*>(src)[tid];
    float s = v.x * v.x + v.y * v.y + v.z * v.z + v.w * v.w;
    union { uint2 u; __nv_bfloat162 h[2]; } w;
    w.h[0] = __floats2bfloat162_rn(v.x, v.y);
    w.h[1] = __floats2bfloat162_rn(v.z, v.w);
    reinterpret_cast<uint2*>(dst)[tid] = w.u;
#pragma unroll
    for (int off = 16; off > 0; off >>= 1) s += __shfl_down_sync(0xffffffffu, s, off);
    __shared__ float ws[4];
    if ((tid & 31) == 0) ws[tid >> 5] = s;
    __syncthreads();
    if (tid == 0) *o = ws[0] + ws[1] + ws[2] + ws[3];
}

// merged weight converts: rows < DIM -> w_v, rows >= DIM -> w_o
__global__ void conv_weights(const float* __restrict__ wv, const float* __restrict__ wo,
                             __nv_bfloat16* __restrict__ wvb, __nv_bfloat16* __restrict__ wob) {
    const int row = blockIdx.x;
    const int tid = threadIdx.x;
    const float* src = (row < DIM) ? wv + (size_t)row * DIM
                                   : wo + (size_t)(row - DIM) * DIM;
    __nv_bfloat16* dst = (row < DIM) ? wvb + (size_t)row * DIM
                                     : wob + (size_t)(row - DIM) * DIM;
    const float4 v = reinterpret_cast<const float4*>(src)[tid];
    union { uint2 u; __nv_bfloat162 h[2]; } w;
    w.h[0] = __floats2bfloat162_rn(v.x, v.y);
    w.h[1] = __floats2bfloat162_rn(v.z, v.w);
    reinterpret_cast<uint2*>(dst)[tid] = w.u;
}

// cvec[d] = b_o[d] + dot(w_o[d,:], b_v)
__global__ void cvec_kernel(const float* __restrict__ w_o, const float* __restrict__ b_v,
                            const float* __restrict__ b_o, float* __restrict__ cvec) {
    const int d = blockIdx.x;
    const int tid = threadIdx.x;
    float s = 0.f;
#pragma unroll
    for (int i = tid; i < DIM; i += 128) s += w_o[(size_t)d * DIM + i] * b_v[i];
#pragma unroll
    for (int off = 16; off > 0; off >>= 1) s += __shfl_down_sync(0xffffffffu, s, off);
    __shared__ float ws[4];
    if ((tid & 31) == 0) ws[tid >> 5] = s;
    __syncthreads();
    if (tid == 0) cvec[d] = b_o[d] + ws[0] + ws[1] + ws[2] + ws[3];
}

// ---------------------------------------------------------------------------
extern "C" void kernel_launch(void* const* d_in, const int* in_sizes, int n_in,
                              void* d_out, int out_size)
{
    const float* x     = (const float*)d_in[0];
    const float* pos   = (const float*)d_in[1];
    const float* scale = (const float*)d_in[2];
    const float* w_v   = (const float*)d_in[3];
    const float* b_v   = (const float*)d_in[4];
    const float* w_o   = (const float*)d_in[5];
    const float* b_o   = (const float*)d_in[6];
    float* out = (float*)d_out;

    static float* pp2 = nullptr;
    static float *px2, *pcv, *ppsum;
    static __nv_bfloat16 *pxb, *ppb, *pwvb, *pwob, *pvalb, *pw2b, *pattn;
    static cudaStream_t s1;
    static cudaEvent_t ev0, ev1;
    if (pp2 == nullptr) {
        cudaGetSymbolAddress((void**)&pp2,   g_p2);
        cudaGetSymbolAddress((void**)&px2,   g_x2);
        cudaGetSymbolAddress((void**)&pcv,   g_cvec);
        cudaGetSymbolAddress((void**)&ppsum, g_psum);
        cudaGetSymbolAddress((void**)&pxb,   g_xb);
        cudaGetSymbolAddress((void**)&ppb,   g_pb);
        cudaGetSymbolAddress((void**)&pwvb,  g_wvb);
        cudaGetSymbolAddress((void**)&pwob,  g_wob);
        cudaGetSymbolAddress((void**)&pvalb, g_valb);
        cudaGetSymbolAddress((void**)&pw2b,  g_w2b);
        cudaGetSymbolAddress((void**)&pattn, g_attn);
        cudaFuncSetAttribute(mma_gemm<1>, cudaFuncAttributeMaxDynamicSharedMemorySize, MG_SMEM);
        cudaFuncSetAttribute(mma_gemm<2>, cudaFuncAttributeMaxDynamicSharedMemorySize, MG_SMEM);
        cudaFuncSetAttribute(mma_gemm<4>, cudaFuncAttributeMaxDynamicSharedMemorySize, MG_SMEM);
        cudaStreamCreateWithFlags(&s1, cudaStreamNonBlocking);
        cudaEventCreateWithFlags(&ev0, cudaEventDisableTiming);
        cudaEventCreateWithFlags(&ev1, cudaEventDisableTiming);
    }

    // input converts + norms (needed by both branches)
    conv_inputs<<<BT + NNEUR, 128>>>(x, pos, pxb, ppb, px2, pp2);
    cudaEventRecord(ev0, 0);

    // ---- side stream: weight chain (independent of GEMM1) ----
    cudaStreamWaitEvent(s1, ev0, 0);
    conv_weights<<<2 * DIM, 128, 0, s1>>>(w_v, w_o, pwvb, pwob);
    cvec_kernel <<<DIM,     128, 0, s1>>>(w_o, b_v, b_o, pcv);
    // values = pos @ w_v^T           (4096 x 512, K=512, bf16 out)
    mma_gemm<2><<<dim3(DIM / 128, NNEUR / 128), 256, MG_SMEM, s1>>>(
        ppb, pwvb, pvalb, DIM, DIM, DIM, DIM / 32, nullptr, nullptr, nullptr, nullptr);
    // W2^T = w_o @ values^T          (512 x 4096, K=512, bf16 out)
    mma_gemm<2><<<dim3(NNEUR / 128, DIM / 128), 256, MG_SMEM, s1>>>(
        pwob, pvalb, pw2b, DIM, DIM, NNEUR, DIM / 32, nullptr, nullptr, nullptr, nullptr);
    cudaEventRecord(ev1, s1);

    // ---- main stream: e = exp(f(x @ pos^T)) overlaps the side chain ----
    mma_gemm<1><<<dim3(NNEUR / 128, BT / 128), 256, MG_SMEM>>>(
        pxb, ppb, pattn, DIM, DIM, NNEUR, DIM / 32, px2, pp2, scale, ppsum);

    // join, then out = (e @ W2) / S + cvec   (8192 x 512, K=4096, fp32 out;
    // S folded into the GEMM's prologue from psum)
    cudaStreamWaitEvent(0, ev1, 0);
    mma_gemm<4><<<dim3(DIM / 128, BT / 128), 256, MG_SMEM>>>(
        pattn, pw2b, out, NNEUR, NNEUR, DIM, NNEUR / 32, nullptr, nullptr, pcv, ppsum);
}

// round 13
// speedup vs baseline: 1.4362x; 1.0650x over previous
#include <cuda_runtime.h>
#include <cuda_bf16.h>
#include <cuda_fp16.h>
#include <math.h>
#include <stdint.h>

#define DIM    512
#define NNEUR  4096
#define BT     8192   // B*T
#define NBLK1  (NNEUR / 128)   // 32 column-blocks in GEMM1

// ---------------- scratch (device globals; allocation-free) ----------------
__device__ float                       g_p2[NNEUR];
__device__ float                       g_x2[BT];
__device__ float                       g_cvec[DIM];
__device__ __align__(16) float         g_psum[(size_t)BT * NBLK1];     // 1 MB
__device__ __align__(16) __half        g_xh[BT * DIM];                 // 8 MB
__device__ __align__(16) __half        g_ph[NNEUR * DIM];              // 4 MB
__device__ __align__(16) __nv_bfloat16 g_pb[NNEUR * DIM];              // 4 MB
__device__ __align__(16) __nv_bfloat16 g_wvb[DIM * DIM];               // 0.5 MB
__device__ __align__(16) __nv_bfloat16 g_wob[DIM * DIM];               // 0.5 MB
__device__ __align__(16) __nv_bfloat16 g_valb[NNEUR * DIM];            // 4 MB  values
__device__ __align__(16) __nv_bfloat16 g_w2b[DIM * NNEUR];             // 4 MB  W2^T
__device__ __align__(16) __nv_bfloat16 g_attn[(size_t)BT * NNEUR];     // 64 MB (e = exp)

// ---------------- warp-mma helpers (base ISA: sm_80+, no 'a' suffix) -------
__device__ __forceinline__ uint32_t smem_to_u32(const void* p) {
    uint32_t a;
    asm("{ .reg .u64 t; cvta.to.shared.u64 t, %1; cvt.u32.u64 %0, t; }" : "=r"(a) : "l"(p));
    return a;
}
__device__ __forceinline__ void ldsm4(uint32_t& r0, uint32_t& r1, uint32_t& r2,
                                      uint32_t& r3, uint32_t addr) {
    asm volatile("ldmatrix.sync.aligned.m8n8.x4.shared.b16 {%0,%1,%2,%3}, [%4];"
                 : "=r"(r0), "=r"(r1), "=r"(r2), "=r"(r3) : "r"(addr));
}
__device__ __forceinline__ void mma16816(float* c, const uint32_t* a,
                                         uint32_t b0, uint32_t b1) {
    asm volatile(
        "mma.sync.aligned.m16n8k16.row.col.f32.bf16.bf16.f32 "
        "{%0,%1,%2,%3}, {%4,%5,%6,%7}, {%8,%9}, {%0,%1,%2,%3};"
        : "+f"(c[0]), "+f"(c[1]), "+f"(c[2]), "+f"(c[3])
        : "r"(a[0]), "r"(a[1]), "r"(a[2]), "r"(a[3]), "r"(b0), "r"(b1));
}
// fp16-accumulate variant: C/D are 2 regs of f16x2
__device__ __forceinline__ void mma16816h(uint32_t* c, const uint32_t* a,
                                          uint32_t b0, uint32_t b1) {
    asm volatile(
        "mma.sync.aligned.m16n8k16.row.col.f16.f16.f16.f16 "
        "{%0,%1}, {%2,%3,%4,%5}, {%6,%7}, {%0,%1};"
        : "+r"(c[0]), "+r"(c[1])
        : "r"(a[0]), "r"(a[1]), "r"(a[2]), "r"(a[3]), "r"(b0), "r"(b1));
}
__device__ __forceinline__ void cp16(uint32_t dst, const void* src) {
    asm volatile("cp.async.cg.shared.global [%0], [%1], 16;" :: "r"(dst), "l"(src));
}
#define CP_COMMIT() asm volatile("cp.async.commit_group;" ::: "memory")
#define CP_WAIT(n)  asm volatile("cp.async.wait_group %0;" :: "n"(n) : "memory")

// swizzled smem offset for 64B rows (4 x 16B chunks), conflict-free ldmatrix
__device__ __forceinline__ uint32_t swz_off(int row, int chunk) {
    return (uint32_t)(row * 64 + ((chunk ^ ((row >> 1) & 3)) << 4));
}

static constexpr int MG_STAGES = 4;
static constexpr int MG_SMEM   = MG_STAGES * 16384;   // 64 KB dynamic

// ---------------------------------------------------------------------------
// gemm1_f16: e = exp(interaction(x @ pos^T)), fp16 in, fp16 acc (rate probe).
// Same 128x128x32 tiling / 4-stage constant-folded pipeline as mma_gemm.
// niter = DIM/32 = 16.
// ---------------------------------------------------------------------------
__global__ __launch_bounds__(256) void gemm1_f16(
    const __half* __restrict__ A, const __half* __restrict__ B,
    __nv_bfloat16* __restrict__ Cb,
    const float* __restrict__ x2, const float* __restrict__ p2,
    const float* __restrict__ scale, float* __restrict__ psum)
{
    extern __shared__ __align__(128) char dsm[];
    __shared__ float p2s[128], scs[128];
    __shared__ float bsum[4][128];

    const int tid  = threadIdx.x;
    const int lane = tid & 31, wid = tid >> 5;
    const int warp_m = wid >> 2, warp_n = wid & 3;
    const int bm = blockIdx.y * 128, bn = blockIdx.x * 128;
    constexpr int NITER = DIM / 32;    // 16

    if (tid < 128) {
        p2s[tid] = p2[bn + tid];
        scs[tid] = scale[bn + tid];
    }

    const int lrow = tid >> 2;
    const int lchk = tid & 3;
    const uint32_t su = smem_to_u32(dsm);

    auto issue = [&](int slot, int it) {
        const int k0 = it * 32;
        const uint32_t ab = su + slot * 16384;
        const uint32_t bb = ab + 8192;
#pragma unroll
        for (int h = 0; h < 2; h++) {
            const int r = lrow + h * 64;
            cp16(ab + swz_off(r, lchk), A + (size_t)(bm + r) * DIM + k0 + lchk * 8);
            cp16(bb + swz_off(r, lchk), B + (size_t)(bn + r) * DIM + k0 + lchk * 8);
        }
        CP_COMMIT();
    };

    issue(0, 0);
    issue(1, 1);
    issue(2, 2);

    uint32_t acc[4][4][2] = {};        // f16x2 accumulators (zero-init = +0.0h)
    const int rin = lane & 7, matid = lane >> 3;

    for (int itb = 0; itb < NITER; itb += 4) {
#pragma unroll
        for (int j = 0; j < 4; j++) {
            const int it = itb + j;
            CP_WAIT(2);
            __syncthreads();
            if (it + 3 < NITER) issue((j + 3) & 3, it + 3);

            const uint32_t a_s = su + j * 16384;
            const uint32_t b_s = a_s + 8192;
#pragma unroll
            for (int s = 0; s < 2; s++) {
                uint32_t af[4][4], bf[2][4];
#pragma unroll
                for (int mb = 0; mb < 4; mb++) {
                    const int row = warp_m * 64 + mb * 16 + (matid & 1) * 8 + rin;
                    const int chk = s * 2 + (matid >> 1);
                    ldsm4(af[mb][0], af[mb][1], af[mb][2], af[mb][3], a_s + swz_off(row, chk));
                }
#pragma unroll
                for (int nb2 = 0; nb2 < 2; nb2++) {
                    const int row = warp_n * 32 + nb2 * 16 + (matid >> 1) * 8 + rin;
                    const int chk = s * 2 + (matid & 1);
                    ldsm4(bf[nb2][0], bf[nb2][1], bf[nb2][2], bf[nb2][3], b_s + swz_off(row, chk));
                }
#pragma unroll
                for (int mb = 0; mb < 4; mb++)
#pragma unroll
                    for (int nb = 0; nb < 4; nb++)
                        mma16816h(acc[mb][nb], af[mb],
                                  bf[nb >> 1][(nb & 1) * 2], bf[nb >> 1][(nb & 1) * 2 + 1]);
            }
        }
    }

    // ---- interaction epilogue (fp32 math from unpacked fp16 accs) ----
    const int g = lane >> 2, tig = lane & 3;
    float rs[4][2];
#pragma unroll
    for (int mb = 0; mb < 4; mb++) {
        const int r0 = warp_m * 64 + mb * 16 + g;
        const float xa = x2[bm + r0], xb = x2[bm + r0 + 8];
        rs[mb][0] = 0.f; rs[mb][1] = 0.f;
#pragma unroll
        for (int nb = 0; nb < 4; nb++) {
            const int cl = warp_n * 32 + nb * 8 + 2 * tig;
            const float2 ca = __half22float2(*reinterpret_cast<const __half2*>(&acc[mb][nb][0]));
            const float2 cb = __half22float2(*reinterpret_cast<const __half2*>(&acc[mb][nb][1]));
            const float p0 = p2s[cl], p1 = p2s[cl + 1];
            const float s0 = scs[cl], s1 = scs[cl + 1];
            const float q0 = fmaxf(xa - 2.f * ca.x + p0, 0.f);
            const float q1 = fmaxf(xa - 2.f * ca.y + p1, 0.f);
            const float q2 = fmaxf(xb - 2.f * cb.x + p0, 0.f);
            const float q3 = fmaxf(xb - 2.f * cb.y + p1, 0.f);
            const float e0 = __expf(s0 / (sqrtf(q0) + 0.1f));
            const float e1 = __expf(s1 / (sqrtf(q1) + 0.1f));
            const float e2 = __expf(s0 / (sqrtf(q2) + 0.1f));
            const float e3 = __expf(s1 / (sqrtf(q3) + 0.1f));
            rs[mb][0] += e0 + e1;
            rs[mb][1] += e2 + e3;
            *reinterpret_cast<__nv_bfloat162*>(Cb + (size_t)(bm + r0) * NNEUR + bn + cl) =
                __floats2bfloat162_rn(e0, e1);
            *reinterpret_cast<__nv_bfloat162*>(Cb + (size_t)(bm + r0 + 8) * NNEUR + bn + cl) =
                __floats2bfloat162_rn(e2, e3);
        }
    }

    // deterministic per-block row sums
#pragma unroll
    for (int mb = 0; mb < 4; mb++) {
#pragma unroll
        for (int h = 0; h < 2; h++) {
            float v = rs[mb][h];
            v += __shfl_down_sync(0xffffffffu, v, 1);
            v += __shfl_down_sync(0xffffffffu, v, 2);
            if (tig == 0)
                bsum[warp_n][warp_m * 64 + mb * 16 + h * 8 + g] = v;
        }
    }
    __syncthreads();
    if (tid < 128) {
        const float s = bsum[0][tid] + bsum[1][tid] + bsum[2][tid] + bsum[3][tid];
        psum[(size_t)(bm + tid) * NBLK1 + blockIdx.x] = s;
    }
}

// ---------------------------------------------------------------------------
// bf16 mma_gemm (fp32 acc) — EPI 2: plain bf16 out; EPI 4: c*invS + bias -> fp32.
// ---------------------------------------------------------------------------
template <int EPI>
__global__ __launch_bounds__(256) void mma_gemm(
    const __nv_bfloat16* __restrict__ A, const __nv_bfloat16* __restrict__ B,
    void* __restrict__ Cv, int ldA, int ldB, int ldC, int niter,
    const float* __restrict__ colv,   // EPI4: cvec bias
    float* __restrict__ psum)         // EPI4: partial sums in
{
    extern __shared__ __align__(128) char dsm[];
    __shared__ float p2s[128], scs[128];

    const int tid  = threadIdx.x;
    const int lane = tid & 31, wid = tid >> 5;
    const int warp_m = wid >> 2, warp_n = wid & 3;
    const int bm = blockIdx.y * 128, bn = blockIdx.x * 128;

    if (EPI == 4 && tid < 128) scs[tid] = colv[bn + tid];

    const int lrow = tid >> 2;
    const int lchk = tid & 3;
    const uint32_t su = smem_to_u32(dsm);

    auto issue = [&](int slot, int it) {
        const int k0 = it * 32;
        const uint32_t ab = su + slot * 16384;
        const uint32_t bb = ab + 8192;
#pragma unroll
        for (int h = 0; h < 2; h++) {
            const int r = lrow + h * 64;
            cp16(ab + swz_off(r, lchk), A + (size_t)(bm + r) * ldA + k0 + lchk * 8);
            cp16(bb + swz_off(r, lchk), B + (size_t)(bn + r) * ldB + k0 + lchk * 8);
        }
        CP_COMMIT();
    };

    issue(0, 0);
    issue(1, 1);
    issue(2, 2);

    if (EPI == 4 && tid < 128) {
        // invS for this CTA's 128 rows (overlaps the prefetches above)
        const float4* pp = reinterpret_cast<const float4*>(psum + (size_t)(bm + tid) * NBLK1);
        float s = 0.f;
#pragma unroll
        for (int j = 0; j < NBLK1 / 4; j++) {
            const float4 v = pp[j];
            s += v.x + v.y + v.z + v.w;
        }
        p2s[tid] = 1.0f / s;
    }

    float acc[4][4][4] = {};
    const int rin = lane & 7, matid = lane >> 3;

    for (int itb = 0; itb < niter; itb += 4) {
#pragma unroll
        for (int j = 0; j < 4; j++) {
            const int it = itb + j;
            CP_WAIT(2);
            __syncthreads();
            if (it + 3 < niter) issue((j + 3) & 3, it + 3);

            const uint32_t a_s = su + j * 16384;
            const uint32_t b_s = a_s + 8192;
#pragma unroll
            for (int s = 0; s < 2; s++) {
                uint32_t af[4][4], bf[2][4];
#pragma unroll
                for (int mb = 0; mb < 4; mb++) {
                    const int row = warp_m * 64 + mb * 16 + (matid & 1) * 8 + rin;
                    const int chk = s * 2 + (matid >> 1);
                    ldsm4(af[mb][0], af[mb][1], af[mb][2], af[mb][3], a_s + swz_off(row, chk));
                }
#pragma unroll
                for (int nb2 = 0; nb2 < 2; nb2++) {
                    const int row = warp_n * 32 + nb2 * 16 + (matid >> 1) * 8 + rin;
                    const int chk = s * 2 + (matid & 1);
                    ldsm4(bf[nb2][0], bf[nb2][1], bf[nb2][2], bf[nb2][3], b_s + swz_off(row, chk));
                }
#pragma unroll
                for (int mb = 0; mb < 4; mb++)
#pragma unroll
                    for (int nb = 0; nb < 4; nb++)
                        mma16816(acc[mb][nb], af[mb],
                                 bf[nb >> 1][(nb & 1) * 2], bf[nb >> 1][(nb & 1) * 2 + 1]);
            }
        }
    }

    // ---- epilogue ----
    const int g = lane >> 2, tig = lane & 3;
#pragma unroll
    for (int mb = 0; mb < 4; mb++) {
        const int r0 = warp_m * 64 + mb * 16 + g;
        float inva = 0.f, invb = 0.f;
        if (EPI == 4) { inva = p2s[r0]; invb = p2s[r0 + 8]; }
#pragma unroll
        for (int nb = 0; nb < 4; nb++) {
            const int cl = warp_n * 32 + nb * 8 + 2 * tig;
            const float* c = acc[mb][nb];
            if (EPI == 2) {
                __nv_bfloat16* Cb = reinterpret_cast<__nv_bfloat16*>(Cv);
                *reinterpret_cast<__nv_bfloat162*>(Cb + (size_t)(bm + r0) * ldC + bn + cl) =
                    __floats2bfloat162_rn(c[0], c[1]);
                *reinterpret_cast<__nv_bfloat162*>(Cb + (size_t)(bm + r0 + 8) * ldC + bn + cl) =
                    __floats2bfloat162_rn(c[2], c[3]);
            } else {
                const float b0 = scs[cl], b1 = scs[cl + 1];
                float* Cf = reinterpret_cast<float*>(Cv);
                *reinterpret_cast<float2*>(Cf + (size_t)(bm + r0) * ldC + bn + cl) =
                    make_float2(fmaf(c[0], inva, b0), fmaf(c[1], inva, b1));
                *reinterpret_cast<float2*>(Cf + (size_t)(bm + r0 + 8) * ldC + bn + cl) =
                    make_float2(fmaf(c[2], invb, b0), fmaf(c[3], invb, b1));
            }
        }
    }
}

// ---------------------------------------------------------------------------
// conversions
// ---------------------------------------------------------------------------
// merged: x (rows < BT) and pos (rows >= BT): fp32 -> fp16 (+ pos also bf16)
// + row sum-of-squares
__global__ void conv_inputs(const float* __restrict__ x, const float* __restrict__ pos,
                            __half* __restrict__ xh, __half* __restrict__ ph,
                            __nv_bfloat16* __restrict__ pb,
                            float* __restrict__ x2, float* __restrict__ p2) {
    const int row = blockIdx.x;
    const int tid = threadIdx.x;
    const bool isx = (row < BT);
    const int r = isx ? row : row - BT;
    const float* src = isx ? x + (size_t)r * DIM : pos + (size_t)r * DIM;
    const float4 v = reinterpret_cast<const float4*>(src)[tid];
    float s = v.x * v.x + v.y * v.y + v.z * v.z + v.w * v.w;

    union { uint2 u; __half2 h[2]; } wh;
    wh.h[0] = __floats2half2_rn(v.x, v.y);
    wh.h[1] = __floats2half2_rn(v.z, v.w);
    if (isx) {
        reinterpret_cast<uint2*>(xh + (size_t)r * DIM)[tid] = wh.u;
    } else {
        reinterpret_cast<uint2*>(ph + (size_t)r * DIM)[tid] = wh.u;
        union { uint2 u; __nv_bfloat162 h[2]; } wb;
        wb.h[0] = __floats2bfloat162_rn(v.x, v.y);
        wb.h[1] = __floats2bfloat162_rn(v.z, v.w);
        reinterpret_cast<uint2*>(pb + (size_t)r * DIM)[tid] = wb.u;
    }
#pragma unroll
    for (int off = 16; off > 0; off >>= 1) s += __shfl_down_sync(0xffffffffu, s, off);
    __shared__ float ws[4];
    if ((tid & 31) == 0) ws[tid >> 5] = s;
    __syncthreads();
    if (tid == 0) (isx ? x2 : p2)[r] = ws[0] + ws[1] + ws[2] + ws[3];
}

// merged weight converts: rows < DIM -> w_v, rows >= DIM -> w_o
__global__ void conv_weights(const float* __restrict__ wv, const float* __restrict__ wo,
                             __nv_bfloat16* __restrict__ wvb, __nv_bfloat16* __restrict__ wob) {
    const int row = blockIdx.x;
    const int tid = threadIdx.x;
    const float* src = (row < DIM) ? wv + (size_t)row * DIM
                                   : wo + (size_t)(row - DIM) * DIM;
    __nv_bfloat16* dst = (row < DIM) ? wvb + (size_t)row * DIM
                                     : wob + (size_t)(row - DIM) * DIM;
    const float4 v = reinterpret_cast<const float4*>(src)[tid];
    union { uint2 u; __nv_bfloat162 h[2]; } w;
    w.h[0] = __floats2bfloat162_rn(v.x, v.y);
    w.h[1] = __floats2bfloat162_rn(v.z, v.w);
    reinterpret_cast<uint2*>(dst)[tid] = w.u;
}

// cvec[d] = b_o[d] + dot(w_o[d,:], b_v)
__global__ void cvec_kernel(const float* __restrict__ w_o, const float* __restrict__ b_v,
                            const float* __restrict__ b_o, float* __restrict__ cvec) {
    const int d = blockIdx.x;
    const int tid = threadIdx.x;
    float s = 0.f;
#pragma unroll
    for (int i = tid; i < DIM; i += 128) s += w_o[(size_t)d * DIM + i] * b_v[i];
#pragma unroll
    for (int off = 16; off > 0; off >>= 1) s += __shfl_down_sync(0xffffffffu, s, off);
    __shared__ float ws[4];
    if ((tid & 31) == 0) ws[tid >> 5] = s;
    __syncthreads();
    if (tid == 0) cvec[d] = b_o[d] + ws[0] + ws[1] + ws[2] + ws[3];
}

// ---------------------------------------------------------------------------
extern "C" void kernel_launch(void* const* d_in, const int* in_sizes, int n_in,
                              void* d_out, int out_size)
{
    const float* x     = (const float*)d_in[0];
    const float* pos   = (const float*)d_in[1];
    const float* scale = (const float*)d_in[2];
    const float* w_v   = (const float*)d_in[3];
    const float* b_v   = (const float*)d_in[4];
    const float* w_o   = (const float*)d_in[5];
    const float* b_o   = (const float*)d_in[6];
    float* out = (float*)d_out;

    static float* pp2 = nullptr;
    static float *px2, *pcv, *ppsum;
    static __half *pxh, *pph;
    static __nv_bfloat16 *ppb, *pwvb, *pwob, *pvalb, *pw2b, *pattn;
    static cudaStream_t s1;
    static cudaEvent_t ev0, ev1;
    if (pp2 == nullptr) {
        cudaGetSymbolAddress((void**)&pp2,   g_p2);
        cudaGetSymbolAddress((void**)&px2,   g_x2);
        cudaGetSymbolAddress((void**)&pcv,   g_cvec);
        cudaGetSymbolAddress((void**)&ppsum, g_psum);
        cudaGetSymbolAddress((void**)&pxh,   g_xh);
        cudaGetSymbolAddress((void**)&pph,   g_ph);
        cudaGetSymbolAddress((void**)&ppb,   g_pb);
        cudaGetSymbolAddress((void**)&pwvb,  g_wvb);
        cudaGetSymbolAddress((void**)&pwob,  g_wob);
        cudaGetSymbolAddress((void**)&pvalb, g_valb);
        cudaGetSymbolAddress((void**)&pw2b,  g_w2b);
        cudaGetSymbolAddress((void**)&pattn, g_attn);
        cudaFuncSetAttribute(gemm1_f16,   cudaFuncAttributeMaxDynamicSharedMemorySize, MG_SMEM);
        cudaFuncSetAttribute(mma_gemm<2>, cudaFuncAttributeMaxDynamicSharedMemorySize, MG_SMEM);
        cudaFuncSetAttribute(mma_gemm<4>, cudaFuncAttributeMaxDynamicSharedMemorySize, MG_SMEM);
        cudaStreamCreateWithFlags(&s1, cudaStreamNonBlocking);
        cudaEventCreateWithFlags(&ev0, cudaEventDisableTiming);
        cudaEventCreateWithFlags(&ev1, cudaEventDisableTiming);
    }

    // input converts + norms (needed by both branches)
    conv_inputs<<<BT + NNEUR, 128>>>(x, pos, pxh, pph, ppb, px2, pp2);
    cudaEventRecord(ev0, 0);

    // ---- side stream: weight chain (independent of GEMM1) ----
    cudaStreamWaitEvent(s1, ev0, 0);
    conv_weights<<<2 * DIM, 128, 0, s1>>>(w_v, w_o, pwvb, pwob);
    cvec_kernel <<<DIM,     128, 0, s1>>>(w_o, b_v, b_o, pcv);
    // values = pos @ w_v^T           (4096 x 512, K=512, bf16 out)
    mma_gemm<2><<<dim3(DIM / 128, NNEUR / 128), 256, MG_SMEM, s1>>>(
        ppb, pwvb, pvalb, DIM, DIM, DIM, DIM / 32, nullptr, nullptr);
    // W2^T = w_o @ values^T          (512 x 4096, K=512, bf16 out)
    mma_gemm<2><<<dim3(NNEUR / 128, DIM / 128), 256, MG_SMEM, s1>>>(
        pwob, pvalb, pw2b, DIM, DIM, NNEUR, DIM / 32, nullptr, nullptr);
    cudaEventRecord(ev1, s1);

    // ---- main stream: e = exp(f(x @ pos^T)), fp16 MMA (rate probe) ----
    gemm1_f16<<<dim3(NNEUR / 128, BT / 128), 256, MG_SMEM>>>(
        pxh, pph, pattn, px2, pp2, scale, ppsum);

    // join, then out = (e @ W2) / S + cvec   (8192 x 512, K=4096, fp32 out)
    cudaStreamWaitEvent(0, ev1, 0);
    mma_gemm<4><<<dim3(DIM / 128, BT / 128), 256, MG_SMEM>>>(
        pattn, pw2b, out, NNEUR, NNEUR, DIM, NNEUR / 32, pcv, ppsum);
}